// round 5
// baseline (speedup 1.0000x reference)
#include <cuda_runtime.h>
#include <cuda_bf16.h>

#define IMG   256
#define TILE  16
#define NPIX  (IMG*IMG)
#define FCAP  8192          // B*F = 2*4096 faces total
#define NEARP 0.1f
#define FARP  100.0f

// Per-face precomputed data (prep kernel -> raster kernel), device scratch.
// g_edge[f*3+e] = (xa, ya, xb-xa, yb-ya) for edge e of face f
// g_ins [f*3+k] = (inv[k][0], inv[k][1], inv[k][2], z_k)
// g_bbox[f]     = (xmin, xmax, ymin, ymax) with small conservative margin
__device__ float4 g_edge[FCAP*3];
__device__ float4 g_ins [FCAP*3];
__device__ float4 g_bbox[FCAP];

__global__ void prep_kernel(const float* __restrict__ faces, int BF) {
    int f = blockIdx.x * blockDim.x + threadIdx.x;
    if (f >= BF) return;
    const float* v = faces + (size_t)f * 9;
    float x0 = v[0], y0 = v[1], z0 = v[2];
    float x1 = v[3], y1 = v[4], z1 = v[5];
    float x2 = v[6], y2 = v[7], z2 = v[8];

    g_edge[f*3+0] = make_float4(x0, y0, x1 - x0, y1 - y0);
    g_edge[f*3+1] = make_float4(x1, y1, x2 - x1, y2 - y1);
    g_edge[f*3+2] = make_float4(x2, y2, x0 - x2, y0 - y2);

    // det exactly as reference: x2*(y0-y1) + x0*(y1-y2) + x1*(y2-y0), then clamp
    float det = x2*(y0 - y1) + x0*(y1 - y2) + x1*(y2 - y0);
    det = (det >= 0.f) ? fmaxf(det, 1e-10f) : fminf(det, -1e-10f);

    g_ins[f*3+0] = make_float4(__fdiv_rn(y1 - y2, det), __fdiv_rn(x2 - x1, det),
                               __fdiv_rn(x1*y2 - x2*y1, det), z0);
    g_ins[f*3+1] = make_float4(__fdiv_rn(y2 - y0, det), __fdiv_rn(x0 - x2, det),
                               __fdiv_rn(x2*y0 - x0*y2, det), z1);
    g_ins[f*3+2] = make_float4(__fdiv_rn(y0 - y1, det), __fdiv_rn(x1 - x0, det),
                               __fdiv_rn(x0*y1 - x1*y0, det), z2);

    float xmn = fminf(x0, fminf(x1, x2)) - 1e-4f;
    float xmx = fmaxf(x0, fmaxf(x1, x2)) + 1e-4f;
    float ymn = fminf(y0, fminf(y1, y2)) - 1e-4f;
    float ymx = fmaxf(y0, fmaxf(y1, y2)) + 1e-4f;
    g_bbox[f] = make_float4(xmn, xmx, ymn, ymx);
}

__global__ __launch_bounds__(256)
void raster_kernel(const float* __restrict__ tex, float* __restrict__ out,
                   int F, int B) {
    __shared__ int sCand[4096];
    __shared__ int sCount;

    int b  = blockIdx.z;
    int tx = blockIdx.x, ty = blockIdx.y;
    int j  = tx * TILE + threadIdx.x;   // column
    int i  = ty * TILE + threadIdx.y;   // row
    int tid = threadIdx.y * TILE + threadIdx.x;

    // Pixel center (exact: integer numerator, /256 is exact power-of-two)
    float xp = (2.f * j + 1.f - IMG) * (1.f / IMG);
    float yp = -((2.f * i + 1.f - IMG) * (1.f / IMG));

    // Tile pixel-center extents for bbox culling
    float xlo = (2.f * (tx * TILE) + 1.f - IMG) * (1.f / IMG);
    float xhi = xlo + (2.f * (TILE - 1)) * (1.f / IMG);
    float yhi = -((2.f * (ty * TILE) + 1.f - IMG) * (1.f / IMG));
    float ylo = yhi - (2.f * (TILE - 1)) * (1.f / IMG);

    if (tid == 0) sCount = 0;
    __syncthreads();

    int base = b * F;
    // Bin: cull faces by bbox vs tile extent into smem candidate list.
    for (int f = tid; f < F; f += 256) {
        float4 bb = g_bbox[base + f];
        if (bb.x <= xhi && bb.y >= xlo && bb.z <= yhi && bb.w >= ylo) {
            sCand[atomicAdd(&sCount, 1)] = f;
        }
    }
    __syncthreads();
    int nc = sCount;

    float bestZ = FARP;
    int   bestF = -1;
    float bw0 = 0.f, bw1 = 0.f, bw2 = 0.f;

    #pragma unroll 2
    for (int c = 0; c < nc; c++) {
        int f = sCand[c];
        const float4* E = g_edge + (size_t)(base + f) * 3;
        float4 e0 = __ldg(E), e1 = __ldg(E + 1), e2 = __ldg(E + 2);
        // edge = (yp-ya)*(xb-xa) - (xp-xa)*(yb-ya), mimic XLA mul+fma contraction
        float v0 = fmaf(yp - e0.y, e0.z, -((xp - e0.x) * e0.w));
        float v1 = fmaf(yp - e1.y, e1.z, -((xp - e1.x) * e1.w));
        float v2 = fmaf(yp - e2.y, e2.z, -((xp - e2.x) * e2.w));
        if (v0 >= 0.f && v1 >= 0.f && v2 >= 0.f) {
            const float4* I = g_ins + (size_t)(base + f) * 3;
            float4 r0 = __ldg(I), r1 = __ldg(I + 1), r2 = __ldg(I + 2);
            float w0 = fmaf(r0.x, xp, fmaf(r0.y, yp, r0.z));
            float w1 = fmaf(r1.x, xp, fmaf(r1.y, yp, r1.z));
            float w2 = fmaf(r2.x, xp, fmaf(r2.y, yp, r2.z));
            w0 = fminf(fmaxf(w0, 0.f), 1.f);
            w1 = fminf(fmaxf(w1, 0.f), 1.f);
            w2 = fminf(fmaxf(w2, 0.f), 1.f);
            float s = fmaxf((w0 + w1) + w2, 1e-10f);
            w0 = __fdiv_rn(w0, s);
            w1 = __fdiv_rn(w1, s);
            w2 = __fdiv_rn(w2, s);
            float izp = (__fdiv_rn(w0, r0.w) + __fdiv_rn(w1, r1.w)) + __fdiv_rn(w2, r2.w);
            float zp  = __fdiv_rn(1.f, fmaxf(izp, 1e-10f));
            if (zp > NEARP && zp < FARP) {
                // strict < with lowest-face-index tie-break (matches chunked argmin)
                if (zp < bestZ || (zp == bestZ && f < bestF)) {
                    bestZ = zp; bestF = f;
                    bw0 = w0; bw1 = w1; bw2 = w2;
                }
            }
        }
    }

    // Shade winner: trilinear sample of 4x4x4x3 texture
    float cr = 0.f, cg = 0.f, cb = 0.f, alpha = 0.f;
    if (bestF >= 0) {
        alpha = 1.f;
        const float4* I = g_ins + (size_t)(base + bestF) * 3;
        float z0 = __ldg(I).w, z1 = __ldg(I + 1).w, z2 = __ldg(I + 2).w;
        // tif = clip(w*(T-1)*(zp/fz), 0, T-1-EPS), T=4
        float t0 = fminf(fmaxf((bw0 * 3.f) * __fdiv_rn(bestZ, z0), 0.f), 2.999f);
        float t1 = fminf(fmaxf((bw1 * 3.f) * __fdiv_rn(bestZ, z1), 0.f), 2.999f);
        float t2 = fminf(fmaxf((bw2 * 3.f) * __fdiv_rn(bestZ, z2), 0.f), 2.999f);
        int l0 = (int)t0, l1 = (int)t1, l2 = (int)t2;  // floor (t >= 0)
        float f0 = t0 - (float)l0, f1 = t1 - (float)l1, f2 = t2 - (float)l2;
        const float* tb = tex + (size_t)(base + bestF) * 192;  // 4*4*4*3
        #pragma unroll
        for (int pn = 0; pn < 8; pn++) {
            int b0 = pn & 1, b1 = (pn >> 1) & 1, b2 = (pn >> 2) & 1;
            float wc = (b0 ? f0 : 1.f - f0) * (b1 ? f1 : 1.f - f1) * (b2 ? f2 : 1.f - f2);
            const float* tp = tb + (size_t)((((l0 + b0) * 4 + (l1 + b1)) * 4 + (l2 + b2)) * 3);
            cr = fmaf(wc, __ldg(tp + 0), cr);
            cg = fmaf(wc, __ldg(tp + 1), cg);
            cb = fmaf(wc, __ldg(tp + 2), cb);
        }
    }

    // Output: [rgb (B,256,256,3)] [alpha (B,256,256)] [zp (B,256,256)] concatenated
    int p = i * IMG + j;
    size_t P = NPIX;
    float* orgb = out + ((size_t)b * P + p) * 3;
    orgb[0] = cr; orgb[1] = cg; orgb[2] = cb;
    out[(size_t)B * P * 3 + (size_t)b * P + p] = alpha;
    out[(size_t)B * P * 3 + (size_t)B * P + (size_t)b * P + p] = bestZ;
}

extern "C" void kernel_launch(void* const* d_in, const int* in_sizes, int n_in,
                              void* d_out, int out_size) {
    const float* faces = (const float*)d_in[0];   // (B,F,3,3) f32
    const float* tex   = (const float*)d_in[1];   // (B,F,4,4,4,3) f32
    float* out = (float*)d_out;

    int BF = in_sizes[0] / 9;            // B*F
    int B  = out_size / (NPIX * 5);      // rgb(3) + alpha(1) + zp(1) per pixel
    int F  = BF / B;

    prep_kernel<<<(BF + 255) / 256, 256>>>(faces, BF);
    dim3 grid(IMG / TILE, IMG / TILE, B);
    raster_kernel<<<grid, dim3(TILE, TILE)>>>(tex, out, F, B);
}